// round 16
// baseline (speedup 1.0000x reference)
#include <cuda_runtime.h>
#include <cuda_bf16.h>
#include <math.h>

// ---------------------------------------------------------------------------
// MTCNN ONet forward, N=2048. Round 16: R15 with s_off init bug fixed
// (k2 at 256 threads must stride-init all 288 s_off entries).
// ---------------------------------------------------------------------------

#define NIMG 2048

__device__ unsigned g_B1[(size_t)NIMG * 32 * 552];   // tf32 [n][32][23][24]
__device__ unsigned g_B2[(size_t)NIMG * 64 * 120];   // tf32 [n][64][10][12]
__device__ unsigned g_B3[(size_t)NIMG * 64 * 16];    // tf32 [n][64][16]
__device__ unsigned g_B4h[(size_t)NIMG * 1152];      // tf32 hi (fc5 A)
__device__ unsigned g_B4l[(size_t)NIMG * 1152];      // tf32 lo
__device__ float    g_B5[(size_t)NIMG * 256];
__device__ unsigned g_W2T[288 * 72];
__device__ unsigned g_W3T[4 * 144 * 72];
__device__ unsigned g_W6T[256 * 136];
__device__ unsigned g_W5H[256 * 1152];
__device__ unsigned g_W5L[256 * 1152];

#define NEG_INF (-1e30f)

__device__ __forceinline__ unsigned f2tf32(float f) {
    unsigned u;
    asm("cvt.rna.tf32.f32 %0, %1;" : "=r"(u) : "f"(f));
    return u;
}

__device__ __forceinline__ void mma_tf32(float c[4],
    unsigned a0, unsigned a1, unsigned a2, unsigned a3,
    unsigned b0, unsigned b1)
{
    asm volatile(
        "mma.sync.aligned.m16n8k8.row.col.f32.tf32.tf32.f32 "
        "{%0,%1,%2,%3}, {%4,%5,%6,%7}, {%8,%9}, {%0,%1,%2,%3};"
        : "+f"(c[0]), "+f"(c[1]), "+f"(c[2]), "+f"(c[3])
        : "r"(a0), "r"(a1), "r"(a2), "r"(a3), "r"(b0), "r"(b1));
}

// ---------------------------------------------------------------------------
// K0: weight prep (conv2/3/4 tf32 + fc5 hi/lo). 382976 elems.
// ---------------------------------------------------------------------------
__global__ __launch_bounds__(256) void k0_prep(
    const float* __restrict__ c2w, const float* __restrict__ c3w,
    const float* __restrict__ c4w, const float* __restrict__ d5w)
{
    const int i = blockIdx.x * 256 + threadIdx.x;
    if (i < 18432) {
        const int k = i / 64, oc = i - k * 64;
        g_W2T[k * 72 + oc] = f2tf32(c2w[oc * 288 + k]);
    } else if (i < 55296) {
        const int j = i - 18432;
        const int row = j / 64, oc = j - row * 64;
        const int chunk = row / 144, k = row - chunk * 144;
        g_W3T[row * 72 + oc] = f2tf32(c3w[oc * 576 + chunk * 144 + k]);
    } else if (i < 88064) {
        const int j = i - 55296;
        const int k = j >> 7, oc = j & 127;
        g_W6T[k * 136 + oc] = f2tf32(c4w[oc * 256 + k]);
    } else if (i < 382976) {
        const int j = i - 88064;
        const float f = d5w[j];
        const unsigned hb = f2tf32(f);
        g_W5H[j] = hb;
        g_W5L[j] = f2tf32(f - __uint_as_float(hb));
    }
}

// ---------------------------------------------------------------------------
// K1: conv1 + PReLU + pool1 (fp32). Grid (NIMG, 4), 288 thr, 2 CTAs/SM.
// ---------------------------------------------------------------------------
#define K1_SMEM_FLOATS (6912 + 16928 + 216 + 8 + 8)
__global__ __launch_bounds__(288, 2) void k1_conv1_pool(
    const float* __restrict__ x, const float* __restrict__ w,
    const float* __restrict__ bias, const float* __restrict__ alpha)
{
    extern __shared__ float sm1[];
    float* s_in = sm1;
    float* s_cv = sm1 + 6912;
    float* s_w  = s_cv + 16928;
    float* s_b  = s_w + 216;
    float* s_a  = s_b + 8;

    const int n = blockIdx.x;
    const int ocg = blockIdx.y;
    const int tid = threadIdx.x;
    {
        const float4* src = (const float4*)(x + (size_t)n * 6912);
        float4* dst = (float4*)s_in;
        for (int i = tid; i < 6912 / 4; i += 288) dst[i] = src[i];
        if (tid < 216) s_w[tid] = w[ocg * 216 + tid];
        if (tid < 8) {
            s_b[tid] = bias[ocg * 8 + tid];
            s_a[tid] = alpha[ocg * 8 + tid];
        }
    }
    __syncthreads();

    if (tid < 276) {
        const int y = tid / 6;
        const int xg = (tid % 6) * 8;

        float acc[8][8];
#pragma unroll
        for (int o = 0; o < 8; o++)
#pragma unroll
            for (int j = 0; j < 8; j++) acc[o][j] = 0.f;

#pragma unroll
        for (int ic = 0; ic < 3; ic++) {
#pragma unroll
            for (int ky = 0; ky < 3; ky++) {
                const float* row = s_in + ic * 2304 + (y + ky) * 48;
                float xi[10];
#pragma unroll
                for (int j = 0; j < 10; j++) {
                    int c = xg + j;
                    xi[j] = row[c > 47 ? 47 : c];
                }
#pragma unroll
                for (int o = 0; o < 8; o++) {
                    const float* wp = s_w + o * 27 + ic * 9 + ky * 3;
                    float w0 = wp[0], w1 = wp[1], w2 = wp[2];
#pragma unroll
                    for (int j = 0; j < 8; j++)
                        acc[o][j] += xi[j] * w0 + xi[j + 1] * w1 + xi[j + 2] * w2;
                }
            }
        }
#pragma unroll
        for (int o = 0; o < 8; o++) {
            const float b0 = s_b[o], al = s_a[o];
            float* orow = s_cv + o * 2116 + y * 46;
#pragma unroll
            for (int j = 0; j < 8; j++) {
                const int xx = xg + j;
                if (xx < 46) {
                    float v = acc[o][j] + b0;
                    orow[xx] = v >= 0.f ? v : al * v;
                }
            }
        }
    }
    __syncthreads();

    unsigned* ob = g_B1 + (size_t)n * 17664 + (size_t)ocg * 8 * 552;

    // interior pool (py,px < 22): no clamping
    for (int i = tid; i < 8 * 484; i += 288) {
        const int o = i / 484;
        const int rem = i - o * 484;
        const int py = rem / 22;
        const int px = rem - py * 22;
        const float* base = s_cv + o * 2116 + (py * 2) * 46 + px * 2;
        float m = fmaxf(fmaxf(base[0], base[1]), base[2]);
        m = fmaxf(m, fmaxf(fmaxf(base[46], base[47]), base[48]));
        m = fmaxf(m, fmaxf(fmaxf(base[92], base[93]), base[94]));
        ob[o * 552 + py * 24 + px] = f2tf32(m);
    }
    // edge pool (py==22 or px==22): clamped
    for (int i = tid; i < 8 * 45; i += 288) {
        const int o = i / 45;
        const int rem = i - o * 45;
        int py, px;
        if (rem < 23) { py = 22; px = rem; }
        else          { py = rem - 23; px = 22; }
        const float* base = s_cv + o * 2116;
        float m = NEG_INF;
#pragma unroll
        for (int ky = 0; ky < 3; ky++) {
            int cy = py * 2 + ky; cy = cy > 45 ? 45 : cy;
#pragma unroll
            for (int kx = 0; kx < 3; kx++) {
                int cx = px * 2 + kx; cx = cx > 45 ? 45 : cx;
                m = fmaxf(m, base[cy * 46 + cx]);
            }
        }
        ob[o * 552 + py * 24 + px] = f2tf32(m);
    }
}

// ---------------------------------------------------------------------------
// K2: conv2 + PReLU + pool2 via TF32 mma. Grid (NIMG, 2): (image, oc-half).
// 256 threads, 8 warps, 2 CTAs/SM. N=32 per block, w stride 36, s_off int16.
// ---------------------------------------------------------------------------
#define K2_SIN 0
#define K2_SW 17664
#define K2_OFF 28032
#define K2_B 28176
#define K2_A 28208
#define K2_SMEM_FLOATS 28240      // 112960 B -> 2 CTAs/SM
#define K2_CV_STRIDE 448

__global__ __launch_bounds__(256, 2) void k2_conv2_pool(
    const float* __restrict__ bias, const float* __restrict__ alpha)
{
    extern __shared__ float sm2[];
    unsigned* s_in = (unsigned*)(sm2 + K2_SIN);    // [32][23][24] = 17664
    unsigned* s_w  = (unsigned*)(sm2 + K2_SW);     // [288][36]
    short* s_off   = (short*)(sm2 + K2_OFF);       // [288]
    float* s_b     = sm2 + K2_B;                   // 32
    float* s_a     = sm2 + K2_A;                   // 32
    float* s_cv    = sm2;                          // overlay [32][448] = 14336

    const int n = blockIdx.x;
    const int och = blockIdx.y;
    const int t = threadIdx.x;

    {
        const uint4* src = (const uint4*)(g_B1 + (size_t)n * 17664);
        uint4* dst = (uint4*)s_in;
        for (int i = t; i < 4416; i += 256) dst[i] = src[i];
        const uint4* ws = (const uint4*)g_W2T;
        uint4* wd = (uint4*)s_w;
        for (int i = t; i < 2304; i += 256) {
            const int k = i >> 3, q = i & 7;
            wd[k * 9 + q] = ws[k * 18 + och * 8 + q];
        }
        // FIX: 256 threads must cover all 288 entries (strided)
        for (int k = t; k < 288; k += 256) {
            const int ic = k / 9;
            const int r = k - ic * 9;
            s_off[k] = (short)(ic * 552 + (r / 3) * 24 + (r % 3));
        }
        if (t < 32) {
            s_b[t] = bias[och * 32 + t];
            s_a[t] = alpha[och * 32 + t];
        }
    }
    __syncthreads();

    const int warp = t >> 5;
    const int lane = t & 31;
    const int g = lane >> 2;
    const int tq = lane & 3;

    const int ntile = (warp < 4) ? 4 : 3;
    int rb[4][2];
    int mrow[4][2];
#pragma unroll
    for (int mi = 0; mi < 4; mi++) {
        const int mt = warp + 8 * mi;
        int m0 = mt * 16 + g;
        int m1 = m0 + 8;
        mrow[mi][0] = m0; mrow[mi][1] = m1;
        int c0 = m0 > 440 ? 440 : m0;
        int c1 = m1 > 440 ? 440 : m1;
        rb[mi][0] = (c0 / 21) * 24 + (c0 % 21);
        rb[mi][1] = (c1 / 21) * 24 + (c1 % 21);
    }

    float c[4][4][4];
#pragma unroll
    for (int mi = 0; mi < 4; mi++)
#pragma unroll
        for (int nt = 0; nt < 4; nt++)
#pragma unroll
            for (int qq = 0; qq < 4; qq++) c[mi][nt][qq] = 0.f;

#pragma unroll 2
    for (int kt = 0; kt < 36; kt++) {
        const int k0 = kt * 8 + tq;
        const int off0 = s_off[k0];
        const int off1 = s_off[k0 + 4];

        unsigned b0[4], b1[4];
        const unsigned* wb = s_w + k0 * 36 + g;
#pragma unroll
        for (int nt = 0; nt < 4; nt++) {
            b0[nt] = wb[nt * 8];
            b1[nt] = wb[4 * 36 + nt * 8];
        }
#pragma unroll
        for (int mi = 0; mi < 4; mi++) {
            if (mi < ntile) {
                const unsigned a0 = s_in[rb[mi][0] + off0];
                const unsigned a1 = s_in[rb[mi][1] + off0];
                const unsigned a2 = s_in[rb[mi][0] + off1];
                const unsigned a3 = s_in[rb[mi][1] + off1];
#pragma unroll
                for (int nt = 0; nt < 4; nt++)
                    mma_tf32(c[mi][nt], a0, a1, a2, a3, b0[nt], b1[nt]);
            }
        }
    }
    __syncthreads();   // all A/B reads done; overlay writable

#pragma unroll
    for (int mi = 0; mi < 4; mi++) {
        if (mi < ntile) {
#pragma unroll
            for (int nt = 0; nt < 4; nt++) {
                const int oc0 = nt * 8 + 2 * tq;
                const int oc1 = oc0 + 1;
                const float b00 = s_b[oc0], a00 = s_a[oc0];
                const float b01 = s_b[oc1], a01 = s_a[oc1];
#pragma unroll
                for (int h = 0; h < 2; h++) {
                    const int m = mrow[mi][h];
                    if (m < 441) {
                        float v0 = c[mi][nt][2 * h + 0] + b00;
                        float v1 = c[mi][nt][2 * h + 1] + b01;
                        s_cv[oc0 * K2_CV_STRIDE + m] = v0 >= 0.f ? v0 : a00 * v0;
                        s_cv[oc1 * K2_CV_STRIDE + m] = v1 >= 0.f ? v1 : a01 * v1;
                    }
                }
            }
        }
    }
    __syncthreads();

    unsigned* ob = g_B2 + (size_t)n * 7680 + (size_t)och * 32 * 120;
    for (int i = t; i < 3200; i += 256) {
        const int oc = i / 100;
        const int r = i - oc * 100;
        const int py = r / 10;
        const int px = r - py * 10;
        const float* base = s_cv + oc * K2_CV_STRIDE + (py * 2) * 21 + px * 2;
        float m = NEG_INF;
#pragma unroll
        for (int ky = 0; ky < 3; ky++)
#pragma unroll
            for (int kx = 0; kx < 3; kx++)
                m = fmaxf(m, base[ky * 21 + kx]);
        ob[oc * 120 + py * 12 + px] = f2tf32(m);
    }
}

// ---------------------------------------------------------------------------
// K4: conv3 + PReLU + pool3 via TF32 mma. 4 img/block, 256 thr, 2 CTAs/SM.
// ---------------------------------------------------------------------------
#define K4_INH 0
#define K4_WH 7680
#define K4_OFFT 18048
#define K4_BO 18192
#define K4_AO 18256
#define K4_SMEM_FLOATS 18320

__global__ __launch_bounds__(256, 2) void k4_conv3_pool(
    const float* __restrict__ bias, const float* __restrict__ alpha)
{
    extern __shared__ float sm4[];
    unsigned* inh = (unsigned*)(sm4 + K4_INH);   // [4img][16ic][10][12]
    unsigned* wh  = (unsigned*)(sm4 + K4_WH);    // [144][72]
    int* s_off    = (int*)(sm4 + K4_OFFT);
    float* s_b    = sm4 + K4_BO;
    float* s_a    = sm4 + K4_AO;
    float* s_cv   = sm4;                         // overlay [4][64][64]

    const int n0 = blockIdx.x * 4;
    const int t = threadIdx.x;
    const int warp = t >> 5;
    const int lane = t & 31;
    const int g = lane >> 2;
    const int tq = lane & 3;

    if (t < 64) {
        s_b[t] = bias[t];
        s_a[t] = alpha[t];
    }
    if (t < 144) {
        const int ic = t / 9;
        const int r = t - ic * 9;
        s_off[t] = ic * 120 + (r / 3) * 12 + (r % 3);
    }

    int rb[2][2];
#pragma unroll
    for (int mi = 0; mi < 2; mi++) {
        const int mt = 2 * warp + mi;
#pragma unroll
        for (int h = 0; h < 2; h++) {
            const int m = mt * 16 + g + 8 * h;
            const int img = m >> 6;
            const int px = m & 63;
            rb[mi][h] = img * 1920 + (px >> 3) * 12 + (px & 7);
        }
    }

    float c[2][8][4];
#pragma unroll
    for (int mi = 0; mi < 2; mi++)
#pragma unroll
        for (int nt = 0; nt < 8; nt++)
#pragma unroll
            for (int qq = 0; qq < 4; qq++) c[mi][nt][qq] = 0.f;

    for (int chunk = 0; chunk < 4; chunk++) {
        __syncthreads();
        {
            uint4* dst = (uint4*)inh;
            for (int i = t; i < 1920; i += 256) {
                const int im = i / 480, rem = i - im * 480;
                dst[im * 480 + rem] = ((const uint4*)g_B2)[
                    (size_t)(n0 + im) * 1920 + chunk * 480 + rem];
            }
            const uint4* ws = (const uint4*)g_W3T + chunk * 2592;
            uint4* wd = (uint4*)wh;
            for (int i = t; i < 2592; i += 256) wd[i] = ws[i];
        }
        __syncthreads();

#pragma unroll 2
        for (int kt = 0; kt < 18; kt++) {
            const int k0 = kt * 8 + tq;
            const int off0 = s_off[k0];
            const int off1 = s_off[k0 + 4];

            unsigned b0[8], b1[8];
            const unsigned* wb = wh + k0 * 72 + g;
#pragma unroll
            for (int nt = 0; nt < 8; nt++) {
                b0[nt] = wb[nt * 8];
                b1[nt] = wb[4 * 72 + nt * 8];
            }
#pragma unroll
            for (int mi = 0; mi < 2; mi++) {
                const unsigned a0 = inh[rb[mi][0] + off0];
                const unsigned a1 = inh[rb[mi][1] + off0];
                const unsigned a2 = inh[rb[mi][0] + off1];
                const unsigned a3 = inh[rb[mi][1] + off1];
#pragma unroll
                for (int nt = 0; nt < 8; nt++)
                    mma_tf32(c[mi][nt], a0, a1, a2, a3, b0[nt], b1[nt]);
            }
        }
    }
    __syncthreads();

#pragma unroll
    for (int mi = 0; mi < 2; mi++) {
        const int mt = 2 * warp + mi;
#pragma unroll
        for (int nt = 0; nt < 8; nt++) {
            const int oc0 = nt * 8 + 2 * tq;
            const int oc1 = oc0 + 1;
            const float b00 = s_b[oc0], a00 = s_a[oc0];
            const float b01 = s_b[oc1], a01 = s_a[oc1];
#pragma unroll
            for (int h = 0; h < 2; h++) {
                const int m = mt * 16 + g + 8 * h;
                const int img = m >> 6;
                const int px = m & 63;
                float v0 = c[mi][nt][2 * h + 0] + b00;
                float v1 = c[mi][nt][2 * h + 1] + b01;
                s_cv[(img * 64 + oc0) * 64 + px] = v0 >= 0.f ? v0 : a00 * v0;
                s_cv[(img * 64 + oc1) * 64 + px] = v1 >= 0.f ? v1 : a01 * v1;
            }
        }
    }
    __syncthreads();

    for (int i = t; i < 4096; i += 256) {
        const int img = i >> 10;
        const int rem = i & 1023;
        const int oc = rem >> 4;
        const int p = rem & 15;
        const int py = p >> 2;
        const int px = p & 3;
        const float* base = s_cv + (img * 64 + oc) * 64 + py * 16 + px * 2;
        float m = fmaxf(fmaxf(base[0], base[1]), fmaxf(base[8], base[9]));
        g_B3[((size_t)(n0 + img) * 64 + oc) * 16 + p] = f2tf32(m);
    }
}

// ---------------------------------------------------------------------------
// K6: conv4 (64->128,2x2)+PReLU+permute flatten via TF32 mma.
// 8 img/block, 320 threads. Output written as tf32 hi/lo bit-planes.
// ---------------------------------------------------------------------------
#define K6_IN 0
#define K6_W 4096
#define K6_OFF 21504
#define K6_B 21632
#define K6_A 21760
#define K6_SMEM_FLOATS 21888

__global__ __launch_bounds__(320) void k6_conv4(
    const float* __restrict__ bias, const float* __restrict__ alpha)
{
    extern __shared__ float sm6[];
    unsigned* u_in = (unsigned*)(sm6 + K6_IN);
    unsigned* u_w  = (unsigned*)(sm6 + K6_W);
    int* s_off     = (int*)(sm6 + K6_OFF);
    float* s_b     = sm6 + K6_B;
    float* s_a     = sm6 + K6_A;

    const int n0 = blockIdx.x * 8;
    const int t = threadIdx.x;
    const int warp = t >> 5;
    const int lane = t & 31;
    const int g = lane >> 2;
    const int tq = lane & 3;
    const int mt = warp >> 1;
    const int nh = warp & 1;

    if (t < 128) {
        const int k = t;
        const int icl = k >> 2;
        const int ky = (k >> 1) & 1;
        const int kx = k & 1;
        s_off[k] = icl * 16 + ky * 4 + kx;
        s_b[t] = bias[t];
        s_a[t] = alpha[t];
    }

    int rb[2];
#pragma unroll
    for (int h = 0; h < 2; h++) {
        int m = mt * 16 + g + 8 * h;
        if (m > 71) m = 71;
        const int im = m / 9;
        const int p = m - im * 9;
        rb[h] = im * 512 + (p / 3) * 4 + (p % 3);
    }

    float c[8][4];
#pragma unroll
    for (int nt = 0; nt < 8; nt++)
#pragma unroll
        for (int qq = 0; qq < 4; qq++) c[nt][qq] = 0.f;

    for (int chunk = 0; chunk < 2; chunk++) {
        __syncthreads();
        {
            uint4* dst = (uint4*)u_in;
            for (int i = t; i < 1024; i += 320) {
                const int im = i >> 7, rem = i & 127;
                dst[i] = ((const uint4*)g_B3)[
                    (size_t)(n0 + im) * 256 + chunk * 128 + rem];
            }
            const uint4* ws = (const uint4*)g_W6T + chunk * 4352;
            uint4* wd = (uint4*)u_w;
            for (int i = t; i < 4352; i += 320) wd[i] = ws[i];
        }
        __syncthreads();

#pragma unroll 2
        for (int kt = 0; kt < 16; kt++) {
            const int k0 = kt * 8 + tq;
            const int off0 = s_off[k0];
            const int off1 = s_off[k0 + 4];

            unsigned b0[8], b1[8];
            const unsigned* wb = u_w + k0 * 136 + nh * 64 + g;
#pragma unroll
            for (int nt = 0; nt < 8; nt++) {
                b0[nt] = wb[nt * 8];
                b1[nt] = wb[4 * 136 + nt * 8];
            }
            const unsigned a0 = u_in[rb[0] + off0];
            const unsigned a1 = u_in[rb[1] + off0];
            const unsigned a2 = u_in[rb[0] + off1];
            const unsigned a3 = u_in[rb[1] + off1];
#pragma unroll
            for (int nt = 0; nt < 8; nt++)
                mma_tf32(c[nt], a0, a1, a2, a3, b0[nt], b1[nt]);
        }
    }

#pragma unroll
    for (int nt = 0; nt < 8; nt++) {
        const int oc0 = nh * 64 + nt * 8 + 2 * tq;
        const int oc1 = oc0 + 1;
        const float b00 = s_b[oc0], a00 = s_a[oc0];
        const float b01 = s_b[oc1], a01 = s_a[oc1];
#pragma unroll
        for (int h = 0; h < 2; h++) {
            const int m = mt * 16 + g + 8 * h;
            if (m < 72) {
                const int im = m / 9;
                const int p = m - im * 9;
                const int hh = p / 3;
                const int ww = p - hh * 3;
                const size_t base = (size_t)(n0 + im) * 1152 + ww * 384 + hh * 128;
                float v0 = c[nt][2 * h + 0] + b00;
                float v1 = c[nt][2 * h + 1] + b01;
                v0 = v0 >= 0.f ? v0 : a00 * v0;
                v1 = v1 >= 0.f ? v1 : a01 * v1;
                unsigned h0 = f2tf32(v0);
                unsigned h1 = f2tf32(v1);
                g_B4h[base + oc0] = h0;
                g_B4l[base + oc0] = f2tf32(v0 - __uint_as_float(h0));
                g_B4h[base + oc1] = h1;
                g_B4l[base + oc1] = f2tf32(v1 - __uint_as_float(h1));
            }
        }
    }
}

// ---------------------------------------------------------------------------
// K7: fc5 via 3xTF32 mma. Grid (32, 4), 256 thr. All staging = uint4 copies.
// ---------------------------------------------------------------------------
__global__ __launch_bounds__(256) void k7_fc5(
    const float* __restrict__ bias, const float* __restrict__ alpha)
{
    __shared__ unsigned sAh[64 * 36], sAl[64 * 36];
    __shared__ unsigned sBh[64 * 36], sBl[64 * 36];

    const int t = threadIdx.x;
    const int bm = blockIdx.x, bn = blockIdx.y;
    const int warp = t >> 5;
    const int lane = t & 31;
    const int g = lane >> 2;
    const int tq = lane & 3;
    const int w_m = warp & 3;
    const int w_n = warp >> 2;

    float c[4][4];
#pragma unroll
    for (int nt = 0; nt < 4; nt++)
#pragma unroll
        for (int qq = 0; qq < 4; qq++) c[nt][qq] = 0.f;

    for (int slab = 0; slab < 36; slab++) {
        const int k0s = slab * 32;
        __syncthreads();
        for (int j = t; j < 512; j += 256) {
            const int m = j >> 3;
            const int kq = (j & 7) * 4;
            const size_t asrc = (size_t)(bm * 64 + m) * 1152 + k0s + kq;
            const size_t bsrc = (size_t)(bn * 64 + m) * 1152 + k0s + kq;
            *(uint4*)(sAh + m * 36 + kq) = *(const uint4*)(g_B4h + asrc);
            *(uint4*)(sAl + m * 36 + kq) = *(const uint4*)(g_B4l + asrc);
            *(uint4*)(sBh + m * 36 + kq) = *(const uint4*)(g_W5H + bsrc);
            *(uint4*)(sBl + m * 36 + kq) = *(const uint4*)(g_W5L + bsrc);
        }
        __syncthreads();

#pragma unroll
        for (int kt = 0; kt < 4; kt++) {
            const int kk = kt * 8 + tq;
            const int r0 = (w_m * 16 + g) * 36;
            const int r1 = (w_m * 16 + g + 8) * 36;
            const unsigned ah0 = sAh[r0 + kk];
            const unsigned ah1 = sAh[r1 + kk];
            const unsigned ah2 = sAh[r0 + kk + 4];
            const unsigned ah3 = sAh[r1 + kk + 4];
            const unsigned al0 = sAl[r0 + kk];
            const unsigned al1 = sAl[r1 + kk];
            const unsigned al2 = sAl[r0 + kk + 4];
            const unsigned al3 = sAl[r1 + kk + 4];
#pragma unroll
            for (int nt = 0; nt < 4; nt++) {
                const int nr = (w_n * 32 + nt * 8 + g) * 36;
                const unsigned bh0 = sBh[nr + kk];
                const unsigned bh1 = sBh[nr + kk + 4];
                const unsigned bl0 = sBl[nr + kk];
                const unsigned bl1 = sBl[nr + kk + 4];
                mma_tf32(c[nt], ah0, ah1, ah2, ah3, bh0, bh1);
                mma_tf32(c[nt], ah0, ah1, ah2, ah3, bl0, bl1);
                mma_tf32(c[nt], al0, al1, al2, al3, bh0, bh1);
            }
        }
    }

#pragma unroll
    for (int nt = 0; nt < 4; nt++) {
        const int o0 = bn * 64 + w_n * 32 + nt * 8 + 2 * tq;
        const int o1 = o0 + 1;
        const float bi0 = bias[o0], al0 = alpha[o0];
        const float bi1 = bias[o1], al1 = alpha[o1];
#pragma unroll
        for (int h = 0; h < 2; h++) {
            const int m = bm * 64 + w_m * 16 + g + 8 * h;
            float v0 = c[nt][2 * h + 0] + bi0;
            float v1 = c[nt][2 * h + 1] + bi1;
            g_B5[(size_t)m * 256 + o0] = v0 >= 0.f ? v0 : al0 * v0;
            g_B5[(size_t)m * 256 + o1] = v1 >= 0.f ? v1 : al1 * v1;
        }
    }
}

// ---------------------------------------------------------------------------
// K8: heads. One warp per image. out layout: [b: N*4 | c: N*10 | a: N*2]
// ---------------------------------------------------------------------------
__global__ __launch_bounds__(256) void k8_heads(
    const float* __restrict__ w1, const float* __restrict__ b1,
    const float* __restrict__ w2, const float* __restrict__ b2,
    const float* __restrict__ w3, const float* __restrict__ b3,
    float* __restrict__ out)
{
    const int warp = (blockIdx.x * 256 + threadIdx.x) >> 5;
    const int lane = threadIdx.x & 31;
    if (warp >= NIMG) return;
    const float* hv = g_B5 + (size_t)warp * 256;
    float hr[8];
#pragma unroll
    for (int j = 0; j < 8; j++) hr[j] = hv[lane + j * 32];

    auto dot = [&](const float* wrow) {
        float s = 0.f;
#pragma unroll
        for (int j = 0; j < 8; j++) s += hr[j] * wrow[lane + j * 32];
#pragma unroll
        for (int off = 16; off; off >>= 1) s += __shfl_xor_sync(0xffffffffu, s, off);
        return s;
    };

    float* out_b = out;
    float* out_c = out + (size_t)NIMG * 4;
    float* out_a = out + (size_t)NIMG * 14;

    float l0 = dot(w1) + b1[0];
    float l1 = dot(w1 + 256) + b1[1];
    float mx = fmaxf(l0, l1);
    float e0 = expf(l0 - mx), e1 = expf(l1 - mx);
    float inv = 1.f / (e0 + e1);
    if (lane == 0) {
        out_a[warp * 2 + 0] = e0 * inv;
        out_a[warp * 2 + 1] = e1 * inv;
    }
#pragma unroll
    for (int o = 0; o < 4; o++) {
        float v = dot(w2 + o * 256) + b2[o];
        if (lane == 0) out_b[warp * 4 + o] = v;
    }
#pragma unroll
    for (int o = 0; o < 10; o++) {
        float v = dot(w3 + o * 256) + b3[o];
        if (lane == 0) out_c[warp * 10 + o] = v;
    }
}

// ---------------------------------------------------------------------------
extern "C" void kernel_launch(void* const* d_in, const int* in_sizes, int n_in,
                              void* d_out, int out_size)
{
    const float* x    = (const float*)d_in[0];
    const float* c1w  = (const float*)d_in[1];
    const float* c1b  = (const float*)d_in[2];
    const float* a1   = (const float*)d_in[3];
    const float* c2w  = (const float*)d_in[4];
    const float* c2b  = (const float*)d_in[5];
    const float* a2   = (const float*)d_in[6];
    const float* c3w  = (const float*)d_in[7];
    const float* c3b  = (const float*)d_in[8];
    const float* a3   = (const float*)d_in[9];
    const float* c4w  = (const float*)d_in[10];
    const float* c4b  = (const float*)d_in[11];
    const float* a4   = (const float*)d_in[12];
    const float* d5w  = (const float*)d_in[13];
    const float* d5b  = (const float*)d_in[14];
    const float* a5   = (const float*)d_in[15];
    const float* d61w = (const float*)d_in[16];
    const float* d61b = (const float*)d_in[17];
    const float* d62w = (const float*)d_in[18];
    const float* d62b = (const float*)d_in[19];
    const float* d63w = (const float*)d_in[20];
    const float* d63b = (const float*)d_in[21];
    float* out = (float*)d_out;

    cudaFuncSetAttribute(k1_conv1_pool, cudaFuncAttributeMaxDynamicSharedMemorySize,
                         K1_SMEM_FLOATS * 4);
    cudaFuncSetAttribute(k2_conv2_pool, cudaFuncAttributeMaxDynamicSharedMemorySize,
                         K2_SMEM_FLOATS * 4);
    cudaFuncSetAttribute(k4_conv3_pool, cudaFuncAttributeMaxDynamicSharedMemorySize,
                         K4_SMEM_FLOATS * 4);
    cudaFuncSetAttribute(k6_conv4, cudaFuncAttributeMaxDynamicSharedMemorySize,
                         K6_SMEM_FLOATS * 4);

    k0_prep<<<(382976 + 255) / 256, 256>>>(c2w, c3w, c4w, d5w);
    k1_conv1_pool<<<dim3(NIMG, 4), 288, K1_SMEM_FLOATS * 4>>>(x, c1w, c1b, a1);
    k2_conv2_pool<<<dim3(NIMG, 2), 256, K2_SMEM_FLOATS * 4>>>(c2b, a2);
    k4_conv3_pool<<<NIMG / 4, 256, K4_SMEM_FLOATS * 4>>>(c3b, a3);
    k6_conv4<<<NIMG / 8, 320, K6_SMEM_FLOATS * 4>>>(c4b, a4);
    k7_fc5<<<dim3(32, 4), 256>>>(d5b, a5);
    k8_heads<<<(NIMG * 32) / 256, 256>>>(d61w, d61b, d62w, d62b, d63w, d63b, out);
}

// round 17
// speedup vs baseline: 1.1735x; 1.1735x over previous
#include <cuda_runtime.h>
#include <cuda_bf16.h>
#include <math.h>

// ---------------------------------------------------------------------------
// MTCNN ONet forward, N=2048. Round 17: conv1 -> tf32 MMA with prepped
// staging (uint4 copies only); k2 reverted to R14 512-thr. Rest = R14.
// ---------------------------------------------------------------------------

#define NIMG 2048
#define X1N (NIMG * 6912)

__device__ unsigned g_X1T[(size_t)X1N];              // tf32 input [n][3][48][48]
__device__ unsigned g_W1T[1280];                     // tf32 [k 32][40] zero-pad
__device__ unsigned g_B1[(size_t)NIMG * 32 * 552];   // tf32 [n][32][23][24]
__device__ unsigned g_B2[(size_t)NIMG * 64 * 120];   // tf32 [n][64][10][12]
__device__ unsigned g_B3[(size_t)NIMG * 64 * 16];    // tf32 [n][64][16]
__device__ unsigned g_B4h[(size_t)NIMG * 1152];
__device__ unsigned g_B4l[(size_t)NIMG * 1152];
__device__ float    g_B5[(size_t)NIMG * 256];
__device__ unsigned g_W2T[288 * 72];
__device__ unsigned g_W3T[4 * 144 * 72];
__device__ unsigned g_W6T[256 * 136];
__device__ unsigned g_W5H[256 * 1152];
__device__ unsigned g_W5L[256 * 1152];

#define NEG_INF (-1e30f)

__device__ __forceinline__ unsigned f2tf32(float f) {
    unsigned u;
    asm("cvt.rna.tf32.f32 %0, %1;" : "=r"(u) : "f"(f));
    return u;
}

__device__ __forceinline__ void mma_tf32(float c[4],
    unsigned a0, unsigned a1, unsigned a2, unsigned a3,
    unsigned b0, unsigned b1)
{
    asm volatile(
        "mma.sync.aligned.m16n8k8.row.col.f32.tf32.tf32.f32 "
        "{%0,%1,%2,%3}, {%4,%5,%6,%7}, {%8,%9}, {%0,%1,%2,%3};"
        : "+f"(c[0]), "+f"(c[1]), "+f"(c[2]), "+f"(c[3])
        : "r"(a0), "r"(a1), "r"(a2), "r"(a3), "r"(b0), "r"(b1));
}

// ---------------------------------------------------------------------------
// K0: weight prep (conv2/3/4 tf32 + fc5 hi/lo). 382976 elems.
// ---------------------------------------------------------------------------
__global__ __launch_bounds__(256) void k0_prep(
    const float* __restrict__ c2w, const float* __restrict__ c3w,
    const float* __restrict__ c4w, const float* __restrict__ d5w)
{
    const int i = blockIdx.x * 256 + threadIdx.x;
    if (i < 18432) {
        const int k = i / 64, oc = i - k * 64;
        g_W2T[k * 72 + oc] = f2tf32(c2w[oc * 288 + k]);
    } else if (i < 55296) {
        const int j = i - 18432;
        const int row = j / 64, oc = j - row * 64;
        const int chunk = row / 144, k = row - chunk * 144;
        g_W3T[row * 72 + oc] = f2tf32(c3w[oc * 576 + chunk * 144 + k]);
    } else if (i < 88064) {
        const int j = i - 55296;
        const int k = j >> 7, oc = j & 127;
        g_W6T[k * 136 + oc] = f2tf32(c4w[oc * 256 + k]);
    } else if (i < 382976) {
        const int j = i - 88064;
        const float f = d5w[j];
        const unsigned hb = f2tf32(f);
        g_W5H[j] = hb;
        g_W5L[j] = f2tf32(f - __uint_as_float(hb));
    }
}

// ---------------------------------------------------------------------------
// K0b: input + conv1 weight prep (tf32 bits).
// ---------------------------------------------------------------------------
__global__ __launch_bounds__(256) void k0b_prep(
    const float* __restrict__ x, const float* __restrict__ c1w)
{
    const size_t i = (size_t)blockIdx.x * 256 + threadIdx.x;
    if (i < (size_t)X1N) {
        g_X1T[i] = f2tf32(x[i]);
    } else if (i < (size_t)X1N + 1280) {
        const int j = (int)(i - (size_t)X1N);
        const int k = j / 40, c = j - k * 40;
        g_W1T[j] = (c < 32 && k < 27) ? f2tf32(c1w[c * 27 + k]) : 0u;
    }
}

// ---------------------------------------------------------------------------
// K1: conv1 + PReLU + pool1 via TF32 mma. Grid (NIMG, 4), 256 thr, 2 CTA/SM.
// Slab q: conv rows q*12 .. (+13, q=3:+10). GEMM M=598 pad 38 tiles, N=32,
// K=27 pad 32. All staging = uint4 copies; B-frags hoisted (32 regs).
// ---------------------------------------------------------------------------
#define K1_IN 0
#define K1_W 2160
#define K1_OFFT 3440
#define K1_B 3472
#define K1_A 3504
#define K1_CV 3536
#define K1_SMEM_FLOATS (K1_CV + 32 * 624)   // 23504 f = 94016 B

__global__ __launch_bounds__(256, 2) void k1_conv1_pool(
    const float* __restrict__ bias, const float* __restrict__ alpha)
{
    extern __shared__ float sm1[];
    unsigned* u_in = (unsigned*)(sm1 + K1_IN);   // [3][15][48]
    unsigned* u_w  = (unsigned*)(sm1 + K1_W);    // [32][40]
    int* s_off     = (int*)(sm1 + K1_OFFT);
    float* s_b     = sm1 + K1_B;
    float* s_a     = sm1 + K1_A;
    float* s_cv    = sm1 + K1_CV;                // [32][624]

    const int n = blockIdx.x;
    const int q = blockIdx.y;
    const int r0 = q * 12;
    const int nrows = (q == 3) ? 10 : 13;
    const int mlim = nrows * 46;
    const int t = threadIdx.x;
    const int warp = t >> 5;
    const int lane = t & 31;
    const int g = lane >> 2;
    const int tq = lane & 3;

    {
        const uint4* xs = (const uint4*)(g_X1T + (size_t)n * 6912);
        uint4* di = (uint4*)u_in;
        for (int i = t; i < 540; i += 256) {
            const int ic = i / 180;
            const int rem = i - ic * 180;
            const int rl = rem / 12;
            const int c4 = rem - rl * 12;
            const int grow = r0 + rl;
            di[i] = (grow < 48) ? xs[ic * 576 + grow * 12 + c4]
                                : make_uint4(0u, 0u, 0u, 0u);
        }
        const uint4* ws = (const uint4*)g_W1T;
        uint4* dw = (uint4*)u_w;
        for (int i = t; i < 320; i += 256) dw[i] = ws[i];
        if (t < 32) {
            const int k = t;
            const int ic = k / 9;
            const int r = k - ic * 9;
            s_off[t] = (k < 27) ? (ic * 720 + (r / 3) * 48 + (r % 3)) : 0;
            s_b[t] = bias[t];
            s_a[t] = alpha[t];
        }
    }
    __syncthreads();

    // hoist B fragments and offsets
    unsigned b0[4][4], b1[4][4];
    int off0[4], off1[4];
#pragma unroll
    for (int kt = 0; kt < 4; kt++) {
        const int k0 = kt * 8 + tq;
        off0[kt] = s_off[k0];
        off1[kt] = s_off[k0 + 4];
        const unsigned* wb = u_w + k0 * 40 + g;
#pragma unroll
        for (int nt = 0; nt < 4; nt++) {
            b0[kt][nt] = wb[nt * 8];
            b1[kt][nt] = wb[4 * 40 + nt * 8];
        }
    }

    // per-warp m-tiles: tile = warp + 8j
    for (int j = 0; j < 5; j++) {
        const int tile = warp + 8 * j;
        if (tile >= 38) break;

        int rbl[2], ml[2];
#pragma unroll
        for (int h = 0; h < 2; h++) {
            int m = tile * 16 + g + 8 * h;
            ml[h] = m;
            if (m > 607) m = 607;
            const int ry = m / 46;
            const int cx = m - ry * 46;
            rbl[h] = ry * 48 + cx;
        }

        float c[4][4];
#pragma unroll
        for (int nt = 0; nt < 4; nt++)
#pragma unroll
            for (int qq = 0; qq < 4; qq++) c[nt][qq] = 0.f;

#pragma unroll
        for (int kt = 0; kt < 4; kt++) {
            const unsigned a0 = u_in[rbl[0] + off0[kt]];
            const unsigned a1 = u_in[rbl[1] + off0[kt]];
            const unsigned a2 = u_in[rbl[0] + off1[kt]];
            const unsigned a3 = u_in[rbl[1] + off1[kt]];
#pragma unroll
            for (int nt = 0; nt < 4; nt++)
                mma_tf32(c[nt], a0, a1, a2, a3, b0[kt][nt], b1[kt][nt]);
        }

        // epilogue: bias + PReLU -> s_cv (disjoint from staging, no hazard)
#pragma unroll
        for (int nt = 0; nt < 4; nt++) {
            const int oc0 = nt * 8 + 2 * tq;
            const int oc1 = oc0 + 1;
            const float b00 = s_b[oc0], a00 = s_a[oc0];
            const float b01 = s_b[oc1], a01 = s_a[oc1];
#pragma unroll
            for (int h = 0; h < 2; h++) {
                const int m = ml[h];
                if (m < mlim) {
                    const int ry = m / 46;
                    const int cx = m - ry * 46;
                    float v0 = c[nt][2 * h + 0] + b00;
                    float v1 = c[nt][2 * h + 1] + b01;
                    s_cv[oc0 * 624 + ry * 48 + cx] = v0 >= 0.f ? v0 : a00 * v0;
                    s_cv[oc1 * 624 + ry * 48 + cx] = v1 >= 0.f ? v1 : a01 * v1;
                }
            }
        }
    }
    __syncthreads();

    // pool(3,2,ceil): pooled rows q*6 .. q*6+5 (q=3: 18..22)
    unsigned* ob = g_B1 + (size_t)n * 17664;
    for (int i = t; i < 4416; i += 256) {
        const int oc = i / 138;
        const int rem = i - oc * 138;
        const int pyl = rem / 23;
        const int px = rem - pyl * 23;
        const int py = q * 6 + pyl;
        if (py < 23) {
            float m = NEG_INF;
#pragma unroll
            for (int ky = 0; ky < 3; ky++) {
                int ryl = 2 * pyl + ky;
                if (ryl > nrows - 1) ryl = nrows - 1;
#pragma unroll
                for (int kx = 0; kx < 3; kx++) {
                    int cx = 2 * px + kx;
                    if (cx > 45) cx = 45;
                    m = fmaxf(m, s_cv[oc * 624 + ryl * 48 + cx]);
                }
            }
            ob[oc * 552 + py * 24 + px] = f2tf32(m);
        }
    }
}

// ---------------------------------------------------------------------------
// K2: conv2 + PReLU + pool2 via TF32 mma. One image/block, 512 threads (R14).
// ---------------------------------------------------------------------------
#define K2_STW 72
#define K2_SIN_SZ 17728
#define K2_SW_OFF K2_SIN_SZ
#define K2_SW_SZ (288 * K2_STW)
#define K2_OFF_OFF (K2_SW_OFF + K2_SW_SZ)
#define K2_B_OFF (K2_OFF_OFF + 288)
#define K2_A_OFF (K2_B_OFF + 64)
#define K2_SMEM_FLOATS (K2_A_OFF + 64)
#define K2_CV_STRIDE 448

__global__ __launch_bounds__(512, 1) void k2_conv2_pool(
    const float* __restrict__ bias, const float* __restrict__ alpha)
{
    extern __shared__ float sm2[];
    float* s_in = sm2;
    float* s_w  = sm2 + K2_SW_OFF;
    int*   s_off = (int*)(sm2 + K2_OFF_OFF);
    float* s_b  = sm2 + K2_B_OFF;
    float* s_a  = sm2 + K2_A_OFF;
    float* s_cv = sm2;

    const int n = blockIdx.x;
    const int t = threadIdx.x;

    {
        const uint4* src = (const uint4*)(g_B1 + (size_t)n * 17664);
        uint4* dst = (uint4*)s_in;
        for (int i = t; i < 4416; i += 512) dst[i] = src[i];
        const uint4* ws = (const uint4*)g_W2T;
        uint4* wd = (uint4*)s_w;
        for (int i = t; i < 5184; i += 512) wd[i] = ws[i];
        if (t < 288) {
            const int k = t;
            const int ic = k / 9;
            const int r = k - ic * 9;
            s_off[k] = ic * 552 + (r / 3) * 24 + (r % 3);
        }
        if (t < 64) {
            s_b[t] = bias[t];
            s_a[t] = alpha[t];
        }
    }
    __syncthreads();

    const int warp = t >> 5;
    const int lane = t & 31;
    const int g = lane >> 2;
    const int tq = lane & 3;

    const int ntile2 = (warp < 12) ? 2 : 1;
    int rb[2][2];
    int mrow[2][2];
#pragma unroll
    for (int mi = 0; mi < 2; mi++) {
        const int mt = (mi == 0) ? warp : (16 + warp);
        int m0 = mt * 16 + g;
        int m1 = m0 + 8;
        mrow[mi][0] = m0; mrow[mi][1] = m1;
        int c0 = m0 > 440 ? 440 : m0;
        int c1 = m1 > 440 ? 440 : m1;
        rb[mi][0] = (c0 / 21) * 24 + (c0 % 21);
        rb[mi][1] = (c1 / 21) * 24 + (c1 % 21);
    }

    float c[2][8][4];
#pragma unroll
    for (int mi = 0; mi < 2; mi++)
#pragma unroll
        for (int nt = 0; nt < 8; nt++)
#pragma unroll
            for (int qq = 0; qq < 4; qq++) c[mi][nt][qq] = 0.f;

    const unsigned* u_in = (const unsigned*)s_in;
    const unsigned* u_w = (const unsigned*)s_w;

#pragma unroll 2
    for (int kt = 0; kt < 36; kt++) {
        const int k0 = kt * 8 + tq;
        const int off0 = s_off[k0];
        const int off1 = s_off[k0 + 4];

        unsigned b0[8], b1[8];
        const unsigned* wb = u_w + k0 * K2_STW + g;
#pragma unroll
        for (int nt = 0; nt < 8; nt++) {
            b0[nt] = wb[nt * 8];
            b1[nt] = wb[4 * K2_STW + nt * 8];
        }
#pragma unroll
        for (int mi = 0; mi < 2; mi++) {
            if (mi < ntile2) {
                const unsigned a0 = u_in[rb[mi][0] + off0];
                const unsigned a1 = u_in[rb[mi][1] + off0];
                const unsigned a2 = u_in[rb[mi][0] + off1];
                const unsigned a3 = u_in[rb[mi][1] + off1];
#pragma unroll
                for (int nt = 0; nt < 8; nt++)
                    mma_tf32(c[mi][nt], a0, a1, a2, a3, b0[nt], b1[nt]);
            }
        }
    }
    __syncthreads();

#pragma unroll
    for (int mi = 0; mi < 2; mi++) {
        if (mi < ntile2) {
#pragma unroll
            for (int nt = 0; nt < 8; nt++) {
                const int oc0 = nt * 8 + 2 * tq;
                const int oc1 = oc0 + 1;
                const float b00 = s_b[oc0], a00 = s_a[oc0];
                const float b01 = s_b[oc1], a01 = s_a[oc1];
#pragma unroll
                for (int h = 0; h < 2; h++) {
                    const int m = mrow[mi][h];
                    if (m < 441) {
                        float v0 = c[mi][nt][2 * h + 0] + b00;
                        float v1 = c[mi][nt][2 * h + 1] + b01;
                        s_cv[oc0 * K2_CV_STRIDE + m] = v0 >= 0.f ? v0 : a00 * v0;
                        s_cv[oc1 * K2_CV_STRIDE + m] = v1 >= 0.f ? v1 : a01 * v1;
                    }
                }
            }
        }
    }
    __syncthreads();

    unsigned* ob = g_B2 + (size_t)n * 7680;
    for (int i = t; i < 6400; i += 512) {
        const int oc = i / 100;
        const int r = i - oc * 100;
        const int py = r / 10;
        const int px = r - py * 10;
        const float* base = s_cv + oc * K2_CV_STRIDE + (py * 2) * 21 + px * 2;
        float m = NEG_INF;
#pragma unroll
        for (int ky = 0; ky < 3; ky++)
#pragma unroll
            for (int kx = 0; kx < 3; kx++)
                m = fmaxf(m, base[ky * 21 + kx]);
        ob[oc * 120 + py * 12 + px] = f2tf32(m);
    }
}

// ---------------------------------------------------------------------------
// K4: conv3 + PReLU + pool3 via TF32 mma. 4 img/block, 256 thr, 2 CTAs/SM.
// ---------------------------------------------------------------------------
#define K4_INH 0
#define K4_WH 7680
#define K4_OFFT 18048
#define K4_BO 18192
#define K4_AO 18256
#define K4_SMEM_FLOATS 18320

__global__ __launch_bounds__(256, 2) void k4_conv3_pool(
    const float* __restrict__ bias, const float* __restrict__ alpha)
{
    extern __shared__ float sm4[];
    unsigned* inh = (unsigned*)(sm4 + K4_INH);
    unsigned* wh  = (unsigned*)(sm4 + K4_WH);
    int* s_off    = (int*)(sm4 + K4_OFFT);
    float* s_b    = sm4 + K4_BO;
    float* s_a    = sm4 + K4_AO;
    float* s_cv   = sm4;

    const int n0 = blockIdx.x * 4;
    const int t = threadIdx.x;
    const int warp = t >> 5;
    const int lane = t & 31;
    const int g = lane >> 2;
    const int tq = lane & 3;

    if (t < 64) {
        s_b[t] = bias[t];
        s_a[t] = alpha[t];
    }
    if (t < 144) {
        const int ic = t / 9;
        const int r = t - ic * 9;
        s_off[t] = ic * 120 + (r / 3) * 12 + (r % 3);
    }

    int rb[2][2];
#pragma unroll
    for (int mi = 0; mi < 2; mi++) {
        const int mt = 2 * warp + mi;
#pragma unroll
        for (int h = 0; h < 2; h++) {
            const int m = mt * 16 + g + 8 * h;
            const int img = m >> 6;
            const int px = m & 63;
            rb[mi][h] = img * 1920 + (px >> 3) * 12 + (px & 7);
        }
    }

    float c[2][8][4];
#pragma unroll
    for (int mi = 0; mi < 2; mi++)
#pragma unroll
        for (int nt = 0; nt < 8; nt++)
#pragma unroll
            for (int qq = 0; qq < 4; qq++) c[mi][nt][qq] = 0.f;

    for (int chunk = 0; chunk < 4; chunk++) {
        __syncthreads();
        {
            uint4* dst = (uint4*)inh;
            for (int i = t; i < 1920; i += 256) {
                const int im = i / 480, rem = i - im * 480;
                dst[im * 480 + rem] = ((const uint4*)g_B2)[
                    (size_t)(n0 + im) * 1920 + chunk * 480 + rem];
            }
            const uint4* ws = (const uint4*)g_W3T + chunk * 2592;
            uint4* wd = (uint4*)wh;
            for (int i = t; i < 2592; i += 256) wd[i] = ws[i];
        }
        __syncthreads();

#pragma unroll 2
        for (int kt = 0; kt < 18; kt++) {
            const int k0 = kt * 8 + tq;
            const int off0 = s_off[k0];
            const int off1 = s_off[k0 + 4];

            unsigned b0[8], b1[8];
            const unsigned* wb = wh + k0 * 72 + g;
#pragma unroll
            for (int nt = 0; nt < 8; nt++) {
                b0[nt] = wb[nt * 8];
                b1[nt] = wb[4 * 72 + nt * 8];
            }
#pragma unroll
            for (int mi = 0; mi < 2; mi++) {
                const unsigned a0 = inh[rb[mi][0] + off0];
                const unsigned a1 = inh[rb[mi][1] + off0];
                const unsigned a2 = inh[rb[mi][0] + off1];
                const unsigned a3 = inh[rb[mi][1] + off1];
#pragma unroll
                for (int nt = 0; nt < 8; nt++)
                    mma_tf32(c[mi][nt], a0, a1, a2, a3, b0[nt], b1[nt]);
            }
        }
    }
    __syncthreads();

#pragma unroll
    for (int mi = 0; mi < 2; mi++) {
        const int mt = 2 * warp + mi;
#pragma unroll
        for (int nt = 0; nt < 8; nt++) {
            const int oc0 = nt * 8 + 2 * tq;
            const int oc1 = oc0 + 1;
            const float b00 = s_b[oc0], a00 = s_a[oc0];
            const float b01 = s_b[oc1], a01 = s_a[oc1];
#pragma unroll
            for (int h = 0; h < 2; h++) {
                const int m = mt * 16 + g + 8 * h;
                const int img = m >> 6;
                const int px = m & 63;
                float v0 = c[mi][nt][2 * h + 0] + b00;
                float v1 = c[mi][nt][2 * h + 1] + b01;
                s_cv[(img * 64 + oc0) * 64 + px] = v0 >= 0.f ? v0 : a00 * v0;
                s_cv[(img * 64 + oc1) * 64 + px] = v1 >= 0.f ? v1 : a01 * v1;
            }
        }
    }
    __syncthreads();

    for (int i = t; i < 4096; i += 256) {
        const int img = i >> 10;
        const int rem = i & 1023;
        const int oc = rem >> 4;
        const int p = rem & 15;
        const int py = p >> 2;
        const int px = p & 3;
        const float* base = s_cv + (img * 64 + oc) * 64 + py * 16 + px * 2;
        float m = fmaxf(fmaxf(base[0], base[1]), fmaxf(base[8], base[9]));
        g_B3[((size_t)(n0 + img) * 64 + oc) * 16 + p] = f2tf32(m);
    }
}

// ---------------------------------------------------------------------------
// K6: conv4 (64->128,2x2)+PReLU+permute flatten via TF32 mma.
// ---------------------------------------------------------------------------
#define K6_IN 0
#define K6_W 4096
#define K6_OFF 21504
#define K6_B 21632
#define K6_A 21760
#define K6_SMEM_FLOATS 21888

__global__ __launch_bounds__(320) void k6_conv4(
    const float* __restrict__ bias, const float* __restrict__ alpha)
{
    extern __shared__ float sm6[];
    unsigned* u_in = (unsigned*)(sm6 + K6_IN);
    unsigned* u_w  = (unsigned*)(sm6 + K6_W);
    int* s_off     = (int*)(sm6 + K6_OFF);
    float* s_b     = sm6 + K6_B;
    float* s_a     = sm6 + K6_A;

    const int n0 = blockIdx.x * 8;
    const int t = threadIdx.x;
    const int warp = t >> 5;
    const int lane = t & 31;
    const int g = lane >> 2;
    const int tq = lane & 3;
    const int mt = warp >> 1;
    const int nh = warp & 1;

    if (t < 128) {
        const int k = t;
        const int icl = k >> 2;
        const int ky = (k >> 1) & 1;
        const int kx = k & 1;
        s_off[k] = icl * 16 + ky * 4 + kx;
        s_b[t] = bias[t];
        s_a[t] = alpha[t];
    }

    int rb[2];
#pragma unroll
    for (int h = 0; h < 2; h++) {
        int m = mt * 16 + g + 8 * h;
        if (m > 71) m = 71;
        const int im = m / 9;
        const int p = m - im * 9;
        rb[h] = im * 512 + (p / 3) * 4 + (p % 3);
    }

    float c[8][4];
#pragma unroll
    for (int nt = 0; nt < 8; nt++)
#pragma unroll
        for (int qq = 0; qq < 4; qq++) c[nt][qq] = 0.f;

    for (int chunk = 0; chunk < 2; chunk++) {
        __syncthreads();
        {
            uint4* dst = (uint4*)u_in;
            for (int i = t; i < 1024; i += 320) {
                const int im = i >> 7, rem = i & 127;
                dst[i] = ((const uint4*)g_B3)[
                    (size_t)(n0 + im) * 256 + chunk * 128 + rem];
            }
            const uint4* ws = (const uint4*)g_W6T + chunk * 4352;
            uint4* wd = (uint4*)u_w;
            for (int i = t; i < 4352; i += 320) wd[i] = ws[i];
        }
        __syncthreads();

#pragma unroll 2
        for (int kt = 0; kt < 16; kt++) {
            const int k0 = kt * 8 + tq;
            const int off0 = s_off[k0];
            const int off1 = s_off[k0 + 4];

            unsigned b0[8], b1[8];
            const unsigned* wb = u_w + k0 * 136 + nh * 64 + g;
#pragma unroll
            for (int nt = 0; nt < 8; nt++) {
                b0[nt] = wb[nt * 8];
                b1[nt] = wb[4 * 136 + nt * 8];
            }
            const unsigned a0 = u_in[rb[0] + off0];
            const unsigned a1 = u_in[rb[1] + off0];
            const unsigned a2 = u_in[rb[0] + off1];
            const unsigned a3 = u_in[rb[1] + off1];
#pragma unroll
            for (int nt = 0; nt < 8; nt++)
                mma_tf32(c[nt], a0, a1, a2, a3, b0[nt], b1[nt]);
        }
    }

#pragma unroll
    for (int nt = 0; nt < 8; nt++) {
        const int oc0 = nh * 64 + nt * 8 + 2 * tq;
        const int oc1 = oc0 + 1;
        const float b00 = s_b[oc0], a00 = s_a[oc0];
        const float b01 = s_b[oc1], a01 = s_a[oc1];
#pragma unroll
        for (int h = 0; h < 2; h++) {
            const int m = mt * 16 + g + 8 * h;
            if (m < 72) {
                const int im = m / 9;
                const int p = m - im * 9;
                const int hh = p / 3;
                const int ww = p - hh * 3;
                const size_t base = (size_t)(n0 + im) * 1152 + ww * 384 + hh * 128;
                float v0 = c[nt][2 * h + 0] + b00;
                float v1 = c[nt][2 * h + 1] + b01;
                v0 = v0 >= 0.f ? v0 : a00 * v0;
                v1 = v1 >= 0.f ? v1 : a01 * v1;
                unsigned h0 = f2tf32(v0);
                unsigned h1 = f2tf32(v1);
                g_B4h[base + oc0] = h0;
                g_B4l[base + oc0] = f2tf32(v0 - __uint_as_float(h0));
                g_B4h[base + oc1] = h1;
                g_B4l[base + oc1] = f2tf32(v1 - __uint_as_float(h1));
            }
        }
    }
}

// ---------------------------------------------------------------------------
// K7: fc5 via 3xTF32 mma. Grid (32, 4), 256 thr. All staging = uint4 copies.
// ---------------------------------------------------------------------------
__global__ __launch_bounds__(256) void k7_fc5(
    const float* __restrict__ bias, const float* __restrict__ alpha)
{
    __shared__ unsigned sAh[64 * 36], sAl[64 * 36];
    __shared__ unsigned sBh[64 * 36], sBl[64 * 36];

    const int t = threadIdx.x;
    const int bm = blockIdx.x, bn = blockIdx.y;
    const int warp = t >> 5;
    const int lane = t & 31;
    const int g = lane >> 2;
    const int tq = lane & 3;
    const int w_m = warp & 3;
    const int w_n = warp >> 2;

    float c[4][4];
#pragma unroll
    for (int nt = 0; nt < 4; nt++)
#pragma unroll
        for (int qq = 0; qq < 4; qq++) c[nt][qq] = 0.f;

    for (int slab = 0; slab < 36; slab++) {
        const int k0s = slab * 32;
        __syncthreads();
        for (int j = t; j < 512; j += 256) {
            const int m = j >> 3;
            const int kq = (j & 7) * 4;
            const size_t asrc = (size_t)(bm * 64 + m) * 1152 + k0s + kq;
            const size_t bsrc = (size_t)(bn * 64 + m) * 1152 + k0s + kq;
            *(uint4*)(sAh + m * 36 + kq) = *(const uint4*)(g_B4h + asrc);
            *(uint4*)(sAl + m * 36 + kq) = *(const uint4*)(g_B4l + asrc);
            *(uint4*)(sBh + m * 36 + kq) = *(const uint4*)(g_W5H + bsrc);
            *(uint4*)(sBl + m * 36 + kq) = *(const uint4*)(g_W5L + bsrc);
        }
        __syncthreads();

#pragma unroll
        for (int kt = 0; kt < 4; kt++) {
            const int kk = kt * 8 + tq;
            const int r0 = (w_m * 16 + g) * 36;
            const int r1 = (w_m * 16 + g + 8) * 36;
            const unsigned ah0 = sAh[r0 + kk];
            const unsigned ah1 = sAh[r1 + kk];
            const unsigned ah2 = sAh[r0 + kk + 4];
            const unsigned ah3 = sAh[r1 + kk + 4];
            const unsigned al0 = sAl[r0 + kk];
            const unsigned al1 = sAl[r1 + kk];
            const unsigned al2 = sAl[r0 + kk + 4];
            const unsigned al3 = sAl[r1 + kk + 4];
#pragma unroll
            for (int nt = 0; nt < 4; nt++) {
                const int nr = (w_n * 32 + nt * 8 + g) * 36;
                const unsigned bh0 = sBh[nr + kk];
                const unsigned bh1 = sBh[nr + kk + 4];
                const unsigned bl0 = sBl[nr + kk];
                const unsigned bl1 = sBl[nr + kk + 4];
                mma_tf32(c[nt], ah0, ah1, ah2, ah3, bh0, bh1);
                mma_tf32(c[nt], ah0, ah1, ah2, ah3, bl0, bl1);
                mma_tf32(c[nt], al0, al1, al2, al3, bh0, bh1);
            }
        }
    }

#pragma unroll
    for (int nt = 0; nt < 4; nt++) {
        const int o0 = bn * 64 + w_n * 32 + nt * 8 + 2 * tq;
        const int o1 = o0 + 1;
        const float bi0 = bias[o0], al0 = alpha[o0];
        const float bi1 = bias[o1], al1 = alpha[o1];
#pragma unroll
        for (int h = 0; h < 2; h++) {
            const int m = bm * 64 + w_m * 16 + g + 8 * h;
            float v0 = c[nt][2 * h + 0] + bi0;
            float v1 = c[nt][2 * h + 1] + bi1;
            g_B5[(size_t)m * 256 + o0] = v0 >= 0.f ? v0 : al0 * v0;
            g_B5[(size_t)m * 256 + o1] = v1 >= 0.f ? v1 : al1 * v1;
        }
    }
}

// ---------------------------------------------------------------------------
// K8: heads. One warp per image. out layout: [b: N*4 | c: N*10 | a: N*2]
// ---------------------------------------------------------------------------
__global__ __launch_bounds__(256) void k8_heads(
    const float* __restrict__ w1, const float* __restrict__ b1,
    const float* __restrict__ w2, const float* __restrict__ b2,
    const float* __restrict__ w3, const float* __restrict__ b3,
    float* __restrict__ out)
{
    const int warp = (blockIdx.x * 256 + threadIdx.x) >> 5;
    const int lane = threadIdx.x & 31;
    if (warp >= NIMG) return;
    const float* hv = g_B5 + (size_t)warp * 256;
    float hr[8];
#pragma unroll
    for (int j = 0; j < 8; j++) hr[j] = hv[lane + j * 32];

    auto dot = [&](const float* wrow) {
        float s = 0.f;
#pragma unroll
        for (int j = 0; j < 8; j++) s += hr[j] * wrow[lane + j * 32];
#pragma unroll
        for (int off = 16; off; off >>= 1) s += __shfl_xor_sync(0xffffffffu, s, off);
        return s;
    };

    float* out_b = out;
    float* out_c = out + (size_t)NIMG * 4;
    float* out_a = out + (size_t)NIMG * 14;

    float l0 = dot(w1) + b1[0];
    float l1 = dot(w1 + 256) + b1[1];
    float mx = fmaxf(l0, l1);
    float e0 = expf(l0 - mx), e1 = expf(l1 - mx);
    float inv = 1.f / (e0 + e1);
    if (lane == 0) {
        out_a[warp * 2 + 0] = e0 * inv;
        out_a[warp * 2 + 1] = e1 * inv;
    }
#pragma unroll
    for (int o = 0; o < 4; o++) {
        float v = dot(w2 + o * 256) + b2[o];
        if (lane == 0) out_b[warp * 4 + o] = v;
    }
#pragma unroll
    for (int o = 0; o < 10; o++) {
        float v = dot(w3 + o * 256) + b3[o];
        if (lane == 0) out_c[warp * 10 + o] = v;
    }
}

// ---------------------------------------------------------------------------
extern "C" void kernel_launch(void* const* d_in, const int* in_sizes, int n_in,
                              void* d_out, int out_size)
{
    const float* x    = (const float*)d_in[0];
    const float* c1w  = (const float*)d_in[1];
    const float* c1b  = (const float*)d_in[2];
    const float* a1   = (const float*)d_in[3];
    const float* c2w  = (const float*)d_in[4];
    const float* c2b  = (const float*)d_in[5];
    const float* a2   = (const float*)d_in[6];
    const float* c3w  = (const float*)d_in[7];
    const float* c3b  = (const float*)d_in[8];
    const float* a3   = (const float*)d_in[9];
    const float* c4w  = (const float*)d_in[10];
    const float* c4b  = (const float*)d_in[11];
    const float* a4   = (const float*)d_in[12];
    const float* d5w  = (const float*)d_in[13];
    const float* d5b  = (const float*)d_in[14];
    const float* a5   = (const float*)d_in[15];
    const float* d61w = (const float*)d_in[16];
    const float* d61b = (const float*)d_in[17];
    const float* d62w = (const float*)d_in[18];
    const float* d62b = (const float*)d_in[19];
    const float* d63w = (const float*)d_in[20];
    const float* d63b = (const float*)d_in[21];
    float* out = (float*)d_out;

    cudaFuncSetAttribute(k1_conv1_pool, cudaFuncAttributeMaxDynamicSharedMemorySize,
                         K1_SMEM_FLOATS * 4);
    cudaFuncSetAttribute(k2_conv2_pool, cudaFuncAttributeMaxDynamicSharedMemorySize,
                         K2_SMEM_FLOATS * 4);
    cudaFuncSetAttribute(k4_conv3_pool, cudaFuncAttributeMaxDynamicSharedMemorySize,
                         K4_SMEM_FLOATS * 4);
    cudaFuncSetAttribute(k6_conv4, cudaFuncAttributeMaxDynamicSharedMemorySize,
                         K6_SMEM_FLOATS * 4);

    k0_prep<<<(382976 + 255) / 256, 256>>>(c2w, c3w, c4w, d5w);
    k0b_prep<<<(X1N + 1280 + 255) / 256, 256>>>(x, c1w);
    k1_conv1_pool<<<dim3(NIMG, 4), 256, K1_SMEM_FLOATS * 4>>>(c1b, a1);
    k2_conv2_pool<<<NIMG, 512, K2_SMEM_FLOATS * 4>>>(c2b, a2);
    k4_conv3_pool<<<NIMG / 4, 256, K4_SMEM_FLOATS * 4>>>(c3b, a3);
    k6_conv4<<<NIMG / 8, 320, K6_SMEM_FLOATS * 4>>>(c4b, a4);
    k7_fc5<<<dim3(32, 4), 256>>>(d5b, a5);
    k8_heads<<<(NIMG * 32) / 256, 256>>>(d61w, d61b, d62w, d62b, d63w, d63b, out);
}